// round 6
// baseline (speedup 1.0000x reference)
#include <cuda_runtime.h>
#include <cstdint>

// Problem: out[64,14336] = x[64,4096] @ dequant(W_int)[4096,14336] + bias + x.sum(-1)*u
// W_int int32 in [-8,7]; scales[32,14336] per (group of 128 k-rows, out-col).
//
// Build target is family-generic sm_103 (no 'a') -> tcgen05 unavailable.
// Use mma.sync.m16n8k8 tf32 with rna-rounded operands; scales folded into the
// W int->tf32 conversion on the gmem->smem path.

#define TOKS   64
#define INF    4096
#define OUTF   14336
#define KC     64                 // k-chunk
#define NCHUNK (INF / KC)         // 64
#define NTILE  128
#define NCTA   (OUTF / NTILE)     // 112

// smem strides in 32-bit words, padded for conflict-free fragment LDS:
//   A (x) pattern needs stride % 32 == 4  -> 68
//   B (W) pattern needs stride % 32 == 8  -> 136
#define WS_STRIDE 136
#define XS_STRIDE 68
#define WS_WORDS  (KC * WS_STRIDE)            // 8704
#define XS_WORDS  (KC * XS_STRIDE)            // 4352
#define OFF_WS0   0
#define OFF_WS1   (WS_WORDS)
#define OFF_XS0   (2 * WS_WORDS)
#define OFF_XS1   (2 * WS_WORDS + XS_WORDS)
#define OFF_XSUM  (2 * WS_WORDS + 2 * XS_WORDS)
#define SMEM_WORDS (OFF_XSUM + 64)
#define SMEM_BYTES (SMEM_WORDS * 4)           // 104,960 B

static __device__ __forceinline__ uint32_t f2tf(float f) {
    uint32_t r;
    asm("cvt.rna.tf32.f32 %0, %1;" : "=r"(r) : "f"(f));
    return r;
}

static __device__ __forceinline__ void mma8(float* d, const uint32_t* a, const uint32_t* b) {
    asm volatile(
        "mma.sync.aligned.m16n8k8.row.col.f32.tf32.tf32.f32 "
        "{%0,%1,%2,%3}, {%4,%5,%6,%7}, {%8,%9}, {%0,%1,%2,%3};"
        : "+f"(d[0]), "+f"(d[1]), "+f"(d[2]), "+f"(d[3])
        : "r"(a[0]), "r"(a[1]), "r"(a[2]), "r"(a[3]), "r"(b[0]), "r"(b[1]));
}

__global__ void __launch_bounds__(256, 1)
qbits_kernel(const float* __restrict__ x, const int* __restrict__ W,
             const float* __restrict__ scales, const float* __restrict__ u,
             const float* __restrict__ bias, float* __restrict__ out)
{
    extern __shared__ uint32_t smem[];
    const int tid  = threadIdx.x;
    const int lane = tid & 31;
    const int warp = tid >> 5;          // 0..7
    const int wm   = warp >> 2;         // 0..1  (M side)
    const int wn   = warp & 3;          // 0..3  (N side)
    const int obase = blockIdx.x * NTILE;

    // ---- loader geometry ----
    // W: warp handles k-rows {warp + 8p}, thread handles cols lane*4..+3 (int4, coalesced 512B/warp)
    const int* wptr = W + obase + (lane << 2);
    // x: thread t stages row t>>2, col segment (t&3)*16 .. +15 (4x float4)
    const int xrow    = tid >> 2;
    const int xcolseg = (tid & 3) << 4;
    const float* xptr = x + xrow * INF + xcolseg;

    int4   wreg[8];
    float4 xreg[4];
    float  acc[2][4][4];
    #pragma unroll
    for (int mt = 0; mt < 2; ++mt)
        #pragma unroll
        for (int nt = 0; nt < 4; ++nt)
            #pragma unroll
            for (int j = 0; j < 4; ++j) acc[mt][nt][j] = 0.f;
    float xsum_part = 0.f;

    // ---- prologue: chunk 0 -> regs -> smem buf 0 ----
    {
        #pragma unroll
        for (int p = 0; p < 8; ++p)
            wreg[p] = *(const int4*)(wptr + (warp + 8 * p) * OUTF);
        #pragma unroll
        for (int i = 0; i < 4; ++i)
            xreg[i] = *(const float4*)(xptr + i * 4);

        float4 s = *(const float4*)(scales + obase + (lane << 2));   // group 0
        uint32_t* ws = smem + OFF_WS0;
        #pragma unroll
        for (int p = 0; p < 8; ++p) {
            const int krel = warp + 8 * p;
            uint4 tv;
            tv.x = f2tf((float)wreg[p].x * s.x);
            tv.y = f2tf((float)wreg[p].y * s.y);
            tv.z = f2tf((float)wreg[p].z * s.z);
            tv.w = f2tf((float)wreg[p].w * s.w);
            *(uint4*)(ws + krel * WS_STRIDE + (lane << 2)) = tv;
        }
        uint32_t* xs = smem + OFF_XS0;
        #pragma unroll
        for (int i = 0; i < 4; ++i) {
            float4 v = xreg[i];
            xsum_part += (v.x + v.y) + (v.z + v.w);
            uint4 tv = make_uint4(f2tf(v.x), f2tf(v.y), f2tf(v.z), f2tf(v.w));
            *(uint4*)(xs + xrow * XS_STRIDE + xcolseg + i * 4) = tv;
        }
    }

    // ---- mainloop ----
    for (int c = 0; c < NCHUNK; ++c) {
        const int b = c & 1;
        if (c < NCHUNK - 1) {           // issue next chunk's global loads early
            const int k0n = (c + 1) * KC;
            #pragma unroll
            for (int p = 0; p < 8; ++p)
                wreg[p] = *(const int4*)(wptr + (k0n + warp + 8 * p) * OUTF);
            #pragma unroll
            for (int i = 0; i < 4; ++i)
                xreg[i] = *(const float4*)(xptr + k0n + i * 4);
        }
        __syncthreads();                // smem buf b ready (stores from prev iter)

        const uint32_t* ws = smem + (b ? OFF_WS1 : OFF_WS0);
        const uint32_t* xs = smem + (b ? OFF_XS1 : OFF_XS0);

        #pragma unroll
        for (int ks = 0; ks < 8; ++ks) {
            const int kb = ks * 8;
            const int kk = kb + (lane & 3);
            uint32_t a[2][4], bb[4][2];
            #pragma unroll
            for (int mt = 0; mt < 2; ++mt) {
                const int r = wm * 32 + mt * 16 + (lane >> 2);
                a[mt][0] = xs[r * XS_STRIDE + kk];
                a[mt][1] = xs[(r + 8) * XS_STRIDE + kk];
                a[mt][2] = xs[r * XS_STRIDE + kk + 4];
                a[mt][3] = xs[(r + 8) * XS_STRIDE + kk + 4];
            }
            #pragma unroll
            for (int nt = 0; nt < 4; ++nt) {
                const int col = wn * 32 + nt * 8 + (lane >> 2);
                bb[nt][0] = ws[kk * WS_STRIDE + col];
                bb[nt][1] = ws[(kk + 4) * WS_STRIDE + col];
            }
            #pragma unroll
            for (int mt = 0; mt < 2; ++mt)
                #pragma unroll
                for (int nt = 0; nt < 4; ++nt)
                    mma8(acc[mt][nt], a[mt], bb[nt]);
        }

        if (c < NCHUNK - 1) {           // convert + stage next chunk into other buffer
            const float4 s = *(const float4*)(scales + ((c + 1) >> 1) * OUTF + obase + (lane << 2));
            uint32_t* wsn = smem + (b ? OFF_WS0 : OFF_WS1);
            #pragma unroll
            for (int p = 0; p < 8; ++p) {
                const int krel = warp + 8 * p;
                uint4 tv;
                tv.x = f2tf((float)wreg[p].x * s.x);
                tv.y = f2tf((float)wreg[p].y * s.y);
                tv.z = f2tf((float)wreg[p].z * s.z);
                tv.w = f2tf((float)wreg[p].w * s.w);
                *(uint4*)(wsn + krel * WS_STRIDE + (lane << 2)) = tv;
            }
            uint32_t* xsn = smem + (b ? OFF_XS0 : OFF_XS1);
            #pragma unroll
            for (int i = 0; i < 4; ++i) {
                float4 v = xreg[i];
                xsum_part += (v.x + v.y) + (v.z + v.w);
                uint4 tv = make_uint4(f2tf(v.x), f2tf(v.y), f2tf(v.z), f2tf(v.w));
                *(uint4*)(xsn + xrow * XS_STRIDE + xcolseg + i * 4) = tv;
            }
        }
    }

    // ---- x row-sum: 4 threads per row hold partials; quad-reduce ----
    xsum_part += __shfl_xor_sync(0xFFFFFFFFu, xsum_part, 1);
    xsum_part += __shfl_xor_sync(0xFFFFFFFFu, xsum_part, 2);
    float* xsm = (float*)(smem + OFF_XSUM);
    if ((tid & 3) == 0) xsm[xrow] = xsum_part;
    __syncthreads();

    // ---- epilogue: out = acc + bias + xsum*u ----
    #pragma unroll
    for (int mt = 0; mt < 2; ++mt) {
        #pragma unroll
        for (int jr = 0; jr < 2; ++jr) {
            const int row = wm * 32 + mt * 16 + (lane >> 2) + jr * 8;
            const float xsv = xsm[row];
            #pragma unroll
            for (int nt = 0; nt < 4; ++nt) {
                const int col = obase + wn * 32 + nt * 8 + 2 * (lane & 3);
                const float2 bv = *(const float2*)(bias + col);
                const float2 uv = *(const float2*)(u + col);
                float2 o2;
                o2.x = acc[mt][nt][jr * 2 + 0] + bv.x + xsv * uv.x;
                o2.y = acc[mt][nt][jr * 2 + 1] + bv.y + xsv * uv.y;
                *(float2*)(out + row * OUTF + col) = o2;
            }
        }
    }
}

extern "C" void kernel_launch(void* const* d_in, const int* in_sizes, int n_in,
                              void* d_out, int out_size) {
    const float* x  = (const float*)d_in[0];
    const int*   W  = (const int*)d_in[1];
    const float* sc = (const float*)d_in[2];
    const float* u  = (const float*)d_in[3];
    const float* b  = (const float*)d_in[4];
    float* out = (float*)d_out;

    cudaFuncSetAttribute(qbits_kernel, cudaFuncAttributeMaxDynamicSharedMemorySize,
                         SMEM_BYTES);
    qbits_kernel<<<NCTA, 256, SMEM_BYTES>>>(x, W, sc, u, b, out);
}

// round 8
// speedup vs baseline: 1.1771x; 1.1771x over previous
#include <cuda_runtime.h>
#include <cstdint>

// out[64,14336] = x[64,4096] @ dequant(W_int) + bias + x.sum(-1)*u
// tf32 mma.sync (sm_103 family target: no tcgen05). cp.async 3-stage pipeline,
// W kept int32 in smem, dequant (I2F*scale->tf32) on the fragment path.

#define TOKS   64
#define INF    4096
#define OUTF   14336
#define KC     64
#define NCHUNK (INF / KC)      // 64
#define NTILE  128
#define NCTA   (OUTF / NTILE)  // 112
#define STAGES 3

// padded smem strides (words) for conflict-free fragment LDS:
//  W stride % 32 == 8 -> 136 ; x stride % 32 == 4 -> 68
#define WSTR 136
#define XSTR 68
#define W_STAGE_WORDS (KC * WSTR)          // 8704
#define X_STAGE_WORDS (TOKS * XSTR)        // 4352
#define STAGE_WORDS   (W_STAGE_WORDS + X_STAGE_WORDS)   // 13056
#define STAGE_BYTES   (STAGE_WORDS * 4)                 // 52224
#define W_STAGE_BYTES (W_STAGE_WORDS * 4)               // 34816
#define SMEM_BYTES    (STAGES * STAGE_BYTES)            // 156672

__device__ float g_xtf[TOKS * INF];   // x pre-rounded to tf32
__device__ float g_xsum[TOKS];

static __device__ __forceinline__ uint32_t f2tf(float f) {
    uint32_t r;
    asm("cvt.rna.tf32.f32 %0, %1;" : "=r"(r) : "f"(f));
    return r;
}
static __device__ __forceinline__ uint32_t smem_u32(const void* p) {
    uint32_t a;
    asm("{ .reg .u64 t; cvta.to.shared.u64 t, %1; cvt.u32.u64 %0, t; }" : "=r"(a) : "l"(p));
    return a;
}
static __device__ __forceinline__ void cpasync16(uint32_t dst, const void* src) {
    asm volatile("cp.async.cg.shared.global [%0], [%1], 16;" :: "r"(dst), "l"(src));
}
static __device__ __forceinline__ void mma8(float* d, const uint32_t* a, const uint32_t* b) {
    asm volatile(
        "mma.sync.aligned.m16n8k8.row.col.f32.tf32.tf32.f32 "
        "{%0,%1,%2,%3}, {%4,%5,%6,%7}, {%8,%9}, {%0,%1,%2,%3};"
        : "+f"(d[0]), "+f"(d[1]), "+f"(d[2]), "+f"(d[3])
        : "r"(a[0]), "r"(a[1]), "r"(a[2]), "r"(a[3]), "r"(b[0]), "r"(b[1]));
}

// ---------- prep: x -> tf32 scratch, and per-token row sums ----------
__global__ void __launch_bounds__(256) prep_kernel(const float* __restrict__ x) {
    const int row = blockIdx.x;
    const int t = threadIdx.x;
    const float* xr = x + row * INF;
    float s = 0.f;
    #pragma unroll
    for (int i = 0; i < INF / 256; ++i) {
        const float v = xr[t + i * 256];
        s += v;
        g_xtf[row * INF + t + i * 256] = __uint_as_float(f2tf(v));
    }
    #pragma unroll
    for (int off = 16; off; off >>= 1) s += __shfl_xor_sync(0xffffffffu, s, off);
    __shared__ float red[8];
    if ((t & 31) == 0) red[t >> 5] = s;
    __syncthreads();
    if (t < 8) {
        float v = red[t];
        #pragma unroll
        for (int off = 4; off; off >>= 1) v += __shfl_xor_sync(0xffu, v, off);
        if (t == 0) g_xsum[row] = v;
    }
}

// ---------- main GEMM ----------
__global__ void __launch_bounds__(256, 1)
qbits_kernel(const int* __restrict__ W, const float* __restrict__ scales,
             const float* __restrict__ u, const float* __restrict__ bias,
             float* __restrict__ out)
{
    extern __shared__ uint32_t smem[];
    const uint32_t sbase = smem_u32(smem);
    const int tid  = threadIdx.x;
    const int lane = tid & 31;
    const int warp = tid >> 5;          // 0..7
    const int wm   = warp >> 2;         // 0..1
    const int wn   = warp & 3;          // 0..3
    const int obase = blockIdx.x * NTILE;

    // copy geometry: warp w copies W k-rows {w+8p}, lanes cover 128 cols (16B each)
    const int*   wsrc = W + obase + (lane << 2);
    const float* xsrc = g_xtf + (tid >> 2) * INF + ((tid & 3) << 4);
    const uint32_t wdst_off = (uint32_t)((warp * WSTR + (lane << 2)) * 4);
    const uint32_t xdst_off = (uint32_t)(W_STAGE_BYTES +
                              (((tid >> 2) * XSTR + ((tid & 3) << 4)) * 4));

    float acc[2][4][4];
    #pragma unroll
    for (int mt = 0; mt < 2; ++mt)
        #pragma unroll
        for (int nt = 0; nt < 4; ++nt)
            #pragma unroll
            for (int j = 0; j < 4; ++j) acc[mt][nt][j] = 0.f;

    // ---- issue one chunk's copies into stage s ----
    auto issue = [&](int c, int s) {
        const int k0 = c * KC;
        const uint32_t wb = sbase + (uint32_t)(s * STAGE_BYTES);
        #pragma unroll
        for (int p = 0; p < 8; ++p)
            cpasync16(wb + wdst_off + (uint32_t)(p * 8 * WSTR * 4),
                      wsrc + (k0 + warp + 8 * p) * OUTF);
        #pragma unroll
        for (int i = 0; i < 4; ++i)
            cpasync16(wb + xdst_off + (uint32_t)(i * 16),
                      xsrc + k0 + i * 4);
        asm volatile("cp.async.commit_group;" ::: "memory");
    };

    // prologue: fill stages 0..STAGES-2
    #pragma unroll
    for (int s = 0; s < STAGES - 1; ++s) issue(s, s);

    int st = 0;
    for (int c = 0; c < NCHUNK; ++c) {
        asm volatile("cp.async.wait_group %0;" :: "n"(STAGES - 2) : "memory");
        __syncthreads();                       // stage st holds chunk c
        if (c + STAGES - 1 < NCHUNK) {
            int sn = st + STAGES - 1; if (sn >= STAGES) sn -= STAGES;
            issue(c + STAGES - 1, sn);
        }

        // per-chunk scales for this thread's 4 B columns (group = c/2)
        const float* srow = scales + (c >> 1) * OUTF + obase + wn * 32 + (lane >> 2);
        float sc[4];
        #pragma unroll
        for (int nt = 0; nt < 4; ++nt) sc[nt] = __ldg(srow + nt * 8);

        const uint32_t* ws  = smem + st * STAGE_WORDS;
        const float*    xsm = (const float*)(ws + W_STAGE_WORDS);

        #pragma unroll
        for (int ks = 0; ks < 8; ++ks) {
            const int kk = ks * 8 + (lane & 3);
            uint32_t a[2][4];
            #pragma unroll
            for (int mt = 0; mt < 2; ++mt) {
                const float* xr0 = xsm + (wm * 32 + mt * 16 + (lane >> 2)) * XSTR;
                a[mt][0] = __float_as_uint(xr0[kk]);
                a[mt][1] = __float_as_uint(xr0[8 * XSTR + kk]);
                a[mt][2] = __float_as_uint(xr0[kk + 4]);
                a[mt][3] = __float_as_uint(xr0[8 * XSTR + kk + 4]);
            }
            #pragma unroll
            for (int nt = 0; nt < 4; ++nt) {
                const int col = wn * 32 + nt * 8 + (lane >> 2);
                const int w0 = (int)ws[kk * WSTR + col];
                const int w1 = (int)ws[(kk + 4) * WSTR + col];
                uint32_t bb[2];
                bb[0] = f2tf((float)w0 * sc[nt]);
                bb[1] = f2tf((float)w1 * sc[nt]);
                mma8(acc[0][nt], a[0], bb);
                mma8(acc[1][nt], a[1], bb);
            }
        }
        if (++st == STAGES) st = 0;
    }

    // ---- epilogue: out = acc + bias + xsum*u ----
    #pragma unroll
    for (int mt = 0; mt < 2; ++mt) {
        #pragma unroll
        for (int jr = 0; jr < 2; ++jr) {
            const int row = wm * 32 + mt * 16 + (lane >> 2) + jr * 8;
            const float xsv = g_xsum[row];
            #pragma unroll
            for (int nt = 0; nt < 4; ++nt) {
                const int col = obase + wn * 32 + nt * 8 + 2 * (lane & 3);
                const float2 bv = *(const float2*)(bias + col);
                const float2 uv = *(const float2*)(u + col);
                float2 o2;
                o2.x = acc[mt][nt][jr * 2 + 0] + bv.x + xsv * uv.x;
                o2.y = acc[mt][nt][jr * 2 + 1] + bv.y + xsv * uv.y;
                *(float2*)(out + row * OUTF + col) = o2;
            }
        }
    }
}

extern "C" void kernel_launch(void* const* d_in, const int* in_sizes, int n_in,
                              void* d_out, int out_size) {
    const float* x  = (const float*)d_in[0];
    const int*   W  = (const int*)d_in[1];
    const float* sc = (const float*)d_in[2];
    const float* u  = (const float*)d_in[3];
    const float* b  = (const float*)d_in[4];
    float* out = (float*)d_out;

    cudaFuncSetAttribute(qbits_kernel, cudaFuncAttributeMaxDynamicSharedMemorySize,
                         SMEM_BYTES);
    prep_kernel<<<TOKS, 256>>>(x);
    qbits_kernel<<<NCTA, 256, SMEM_BYTES>>>(W, sc, u, b, out);
}